// round 15
// baseline (speedup 1.0000x reference)
#include <cuda_runtime.h>
#include <cuda_fp16.h>
#include <math.h>
#include <stdint.h>

#define HID   768
#define SEQ   4096
#define BATCH 4
#define MTOT  (BATCH*SEQ)   // 16384

#define BM 128
#define BN 128
#define BKH 64               // halves per stage (128B rows, XOR swizzle, no pad)
#define NSTG 3

#define H_STAGE 32768        // A 128*128B + B 128*128B
#define H_BOFF  16384
#define H_SMEM  (NSTG*H_STAGE)   // 98304 -> 2 CTAs/SM

// output modes for the GEMM epilogue
#define OM_HALF_BIAS    1    // fp16 store, + bias (qkv)
#define OM_HALF_EXP     2    // fp16 store of exp(acc*alpha) + fused row partial sums (scores)
#define OM_F32_ROWSCALE 3    // fp32 store of acc * rowinv[row] (av)

#define NYT (SEQ / BN)       // 32 column tiles per row (scores)

// ---------------- scratch ----------------
__device__ __half g_xh[(size_t)MTOT * HID];
__device__ __half g_wqh[HID * HID];
__device__ __half g_wkh[HID * HID];
__device__ __half g_wvh[HID * HID];
__device__ __half g_q[(size_t)MTOT * HID];
__device__ __half g_k[(size_t)MTOT * HID];
__device__ __half g_v[(size_t)MTOT * HID];
__device__ __half g_vt[(size_t)MTOT * HID];            // [b][d][s]
__device__ __half g_p[(size_t)BATCH * SEQ * SEQ];      // fp16 unnormalized probs
__device__ float  g_ps[(size_t)MTOT * NYT];            // per-tile row partial sums
__device__ float  g_rs[MTOT];                          // 1 / row sum

// ---------------- helpers ----------------
__device__ __forceinline__ uint32_t smem_u32(const void* p) {
    uint32_t a;
    asm("{ .reg .u64 t; cvta.to.shared.u64 t, %1; cvt.u32.u64 %0, t; }" : "=r"(a) : "l"(p));
    return a;
}
__device__ __forceinline__ void cp16(uint32_t dst, const void* src) {
    asm volatile("cp.async.cg.shared.global [%0], [%1], 16;" :: "r"(dst), "l"(src));
}
__device__ __forceinline__ void cp_commit() {
    asm volatile("cp.async.commit_group;" ::: "memory");
}
template<int N> __device__ __forceinline__ void cp_wait() {
    asm volatile("cp.async.wait_group %0;" :: "n"(N) : "memory");
}
__device__ __forceinline__ void mma16(float* c, const unsigned* a, unsigned b0, unsigned b1) {
    asm volatile(
        "mma.sync.aligned.m16n8k16.row.col.f32.f16.f16.f32 "
        "{%0,%1,%2,%3}, {%4,%5,%6,%7}, {%8,%9}, {%0,%1,%2,%3};"
        : "+f"(c[0]), "+f"(c[1]), "+f"(c[2]), "+f"(c[3])
        : "r"(a[0]), "r"(a[1]), "r"(a[2]), "r"(a[3]), "r"(b0), "r"(b1));
}
__device__ __forceinline__ void ldsm4(unsigned& r0, unsigned& r1, unsigned& r2, unsigned& r3,
                                      uint32_t addr) {
    asm volatile("ldmatrix.sync.aligned.m8n8.x4.shared.b16 {%0,%1,%2,%3}, [%4];"
                 : "=r"(r0), "=r"(r1), "=r"(r2), "=r"(r3) : "r"(addr));
}

// ---------------- fp16 compute core: warp 64x32, k-group range [KG0,KG1) ----------------
// smem tile layout: row r (128B) holds k-chunks ch (16B each) at offset ((ch ^ (r&7))<<4)
// wrot rotates each warp's k-group order to de-synchronize the post-barrier LDSM burst.
template<int KG0, int KG1>
__device__ __forceinline__ void compute_kg(
    uint32_t sA, uint32_t sB, float acc[4][4][4],
    int wm, int wn, int lane, int wrot)
{
    const int mrow = lane & 7;
    const int mid  = lane >> 3;

    const int aRow = wm + ((mid & 1) << 3) + mrow;
    const int aSw  = aRow & 7;
    const uint32_t aBase = sA + aRow * 128;
    const int aCh = mid >> 1;

    const int bRow = wn + ((mid >> 1) << 3) + mrow;
    const int bSw  = bRow & 7;
    const uint32_t bBase = sB + bRow * 128;
    const int bCh = mid & 1;

#pragma unroll
    for (int kgi = KG0; kgi < KG1; kgi++) {
        const int c0 = ((kgi + wrot) & 3) * 2;
        unsigned a[4][4], b[4][2];
#pragma unroll
        for (int mi = 0; mi < 4; mi++)
            ldsm4(a[mi][0], a[mi][1], a[mi][2], a[mi][3],
                  aBase + mi * (16 * 128) + (((c0 + aCh) ^ aSw) << 4));
#pragma unroll
        for (int p = 0; p < 2; p++)
            ldsm4(b[2*p][0], b[2*p][1], b[2*p+1][0], b[2*p+1][1],
                  bBase + p * (16 * 128) + (((c0 + bCh) ^ bSw) << 4));
#pragma unroll
        for (int mi = 0; mi < 4; mi++)
#pragma unroll
            for (int ni = 0; ni < 4; ni++)
                mma16(acc[mi][ni], a[mi], b[ni][0], b[ni][1]);
    }
}

// stage loader: 256 threads fill A(128x128B) + B(128x128B) with swizzle
__device__ __forceinline__ void load_stage(
    const __half* __restrict__ A, const __half* __restrict__ Bt,
    int m0, int n0, int lda, int ldb, int k0, uint32_t st, int tid)
{
    const int r  = tid >> 1;
    const int cb = (tid & 1) * 4;
    const int sw = r & 7;
#pragma unroll
    for (int c = 0; c < 4; c++) {
        const int ch = cb + c;
        cp16(st + r * 128 + ((ch ^ sw) << 4),
             A + (size_t)(m0 + r) * lda + k0 + ch * 8);
        cp16(st + H_BOFF + r * 128 + ((ch ^ sw) << 4),
             Bt + (size_t)(n0 + r) * ldb + k0 + ch * 8);
    }
}

// ---------------- fp16 ABT GEMM: D = f(alpha * A * Bt^T) ----------------
template<int OutMode>
__device__ __forceinline__ void gemm_h_body(
    const __half* __restrict__ A, const __half* __restrict__ Bt,
    void* __restrict__ Cv, const float* __restrict__ bias,
    const float* __restrict__ rowinv,
    int K, int lda, int ldb, int ldc, float alpha)
{
    extern __shared__ char smem[];
    const uint32_t sb = smem_u32(smem);

    const int tid  = threadIdx.x;
    const int lane = tid & 31;
    const int warp = tid >> 5;
    const int gid  = lane >> 2;
    const int tig  = lane & 3;
    const int wm   = (warp & 1) * 64;
    const int wn   = (warp >> 1) * 32;
    const int wrot = warp & 3;
    const int m0 = blockIdx.x * BM, n0 = blockIdx.y * BN;

    float acc[4][4][4];
#pragma unroll
    for (int i = 0; i < 4; i++)
#pragma unroll
        for (int j = 0; j < 4; j++)
#pragma unroll
            for (int l = 0; l < 4; l++) acc[i][j][l] = 0.f;

    const int KT = K / BKH;

#pragma unroll
    for (int s = 0; s < NSTG - 1; s++) {
        load_stage(A, Bt, m0, n0, lda, ldb, s * BKH, sb + s * H_STAGE, tid);
        cp_commit();
    }

    for (int kt = 0; kt < KT; kt++) {
        cp_wait<NSTG - 2>();
        __syncthreads();
        const uint32_t sA = sb + (kt % NSTG) * H_STAGE;
        // first k-group (rotated per warp): tensor pipe starts before the load burst
        compute_kg<0, 1>(sA, sA + H_BOFF, acc, wm, wn, lane, wrot);
        if (kt + NSTG - 1 < KT)
            load_stage(A, Bt, m0, n0, lda, ldb, (kt + NSTG - 1) * BKH,
                       sb + ((kt + NSTG - 1) % NSTG) * H_STAGE, tid);
        cp_commit();
        compute_kg<1, 4>(sA, sA + H_BOFF, acc, wm, wn, lane, wrot);
    }

    // epilogue
    float srow[4][2];   // per-mi row partial sums (OM_HALF_EXP only)
#pragma unroll
    for (int mi = 0; mi < 4; mi++) {
        int r0 = m0 + wm + mi * 16 + gid;
        float i0 = 0.f, i1 = 0.f;
        if (OutMode == OM_F32_ROWSCALE) { i0 = rowinv[r0]; i1 = rowinv[r0 + 8]; }
        if (OutMode == OM_HALF_EXP) { srow[mi][0] = 0.f; srow[mi][1] = 0.f; }
#pragma unroll
        for (int ni = 0; ni < 4; ni++) {
            int c0 = n0 + wn + ni * 8 + 2 * tig;
            if (OutMode == OM_HALF_BIAS) {
                float bb0 = bias[c0], bb1 = bias[c0 + 1];
                __half* C = (__half*)Cv;
                *(__half2*)(C + (size_t)r0 * ldc + c0) =
                    __floats2half2_rn(acc[mi][ni][0] + bb0, acc[mi][ni][1] + bb1);
                *(__half2*)(C + (size_t)(r0 + 8) * ldc + c0) =
                    __floats2half2_rn(acc[mi][ni][2] + bb0, acc[mi][ni][3] + bb1);
            } else if (OutMode == OM_HALF_EXP) {
                float e0 = __expf(acc[mi][ni][0] * alpha);
                float e1 = __expf(acc[mi][ni][1] * alpha);
                float e2 = __expf(acc[mi][ni][2] * alpha);
                float e3 = __expf(acc[mi][ni][3] * alpha);
                srow[mi][0] += e0 + e1;
                srow[mi][1] += e2 + e3;
                __half* C = (__half*)Cv;
                *(__half2*)(C + (size_t)r0 * ldc + c0)       = __floats2half2_rn(e0, e1);
                *(__half2*)(C + (size_t)(r0 + 8) * ldc + c0) = __floats2half2_rn(e2, e3);
            } else { // OM_F32_ROWSCALE
                float* C = (float*)Cv;
                *(float2*)(C + (size_t)r0 * ldc + c0) =
                    make_float2(acc[mi][ni][0] * i0, acc[mi][ni][1] * i0);
                *(float2*)(C + (size_t)(r0 + 8) * ldc + c0) =
                    make_float2(acc[mi][ni][2] * i1, acc[mi][ni][3] * i1);
            }
        }
    }

    // fused row-partial reduction (scores only): deterministic fixed-order
    if (OutMode == OM_HALF_EXP) {
        float* ps = (float*)smem;                   // 128 rows x 4 n-warps
        const int wnid = warp >> 1;                 // n-warp index 0..3
        __syncthreads();                            // mainloop smem reuse
#pragma unroll
        for (int mi = 0; mi < 4; mi++) {
#pragma unroll
            for (int h = 0; h < 2; h++) {
                float s = srow[mi][h];
                s += __shfl_xor_sync(0xffffffffu, s, 1);
                s += __shfl_xor_sync(0xffffffffu, s, 2);
                if (tig == 0) {
                    int rl = wm + mi * 16 + gid + h * 8;   // 0..127
                    ps[rl * 4 + wnid] = s;
                }
            }
        }
        __syncthreads();
        if (tid < 128) {
            float s = ps[tid * 4] + ps[tid * 4 + 1] + ps[tid * 4 + 2] + ps[tid * 4 + 3];
            g_ps[(size_t)(blockIdx.z * SEQ + m0 + tid) * NYT + blockIdx.y] = s;
        }
    }
}

// ---------------- kernels ----------------
__global__ void __launch_bounds__(256, 2) qkv_kernel(
    const float* __restrict__ bq, const float* __restrict__ bk,
    const float* __restrict__ bv)
{
    int z = blockIdx.z;
    const __half* W = (z == 0) ? g_wqh : (z == 1) ? g_wkh : g_wvh;
    const float*  b = (z == 0) ? bq : (z == 1) ? bk : bv;
    __half* out     = (z == 0) ? g_q : (z == 1) ? g_k : g_v;
    gemm_h_body<OM_HALF_BIAS>(g_xh, W, out, b, nullptr, HID, HID, HID, HID, 1.0f);
}

__global__ void __launch_bounds__(256, 2) scores_kernel()
{
    int z = blockIdx.z;
    gemm_h_body<OM_HALF_EXP>(g_q + (size_t)z * SEQ * HID,
                             g_k + (size_t)z * SEQ * HID,
                             g_p + (size_t)z * SEQ * SEQ,
                             nullptr, nullptr, HID, HID, HID, SEQ,
                             0.036084391824351615f);
}

__global__ void __launch_bounds__(256, 2) av_kernel(float* __restrict__ out)
{
    int z = blockIdx.z;
    gemm_h_body<OM_F32_ROWSCALE>(g_p  + (size_t)z * SEQ * SEQ,
                                 g_vt + (size_t)z * SEQ * HID,
                                 out  + (size_t)z * SEQ * HID,
                                 nullptr, g_rs + z * SEQ,
                                 SEQ, SEQ, SEQ, HID, 1.0f);
}

// reduce 32 partials per row -> reciprocal (one warp per row, deterministic)
__global__ void __launch_bounds__(256) rowinv_kernel()
{
    const int wid_g = (blockIdx.x * 256 + threadIdx.x) >> 5;   // global warp = row
    const int lane  = threadIdx.x & 31;
    if (wid_g >= MTOT) return;
    float s = g_ps[(size_t)wid_g * NYT + lane];
#pragma unroll
    for (int o = 16; o; o >>= 1) s += __shfl_xor_sync(0xffffffffu, s, o);
    if (lane == 0) g_rs[wid_g] = 1.0f / s;
}

// fp32 -> fp16 conversion: x (z=0..3 slices) + Wq/Wk/Wv (z=4,5,6)
__global__ void __launch_bounds__(256) f2h_all_kernel(
    const float* __restrict__ x,
    const float* __restrict__ Wq, const float* __restrict__ Wk,
    const float* __restrict__ Wv)
{
    const int z = blockIdx.z;
    const float* src;
    __half* dst;
    int n4;
    const int xq = MTOT * HID / 4 / 4;   // quarter of x in float4s
    if (z < 4) { src = x + (size_t)z * xq * 4; dst = g_xh + (size_t)z * xq * 4; n4 = xq; }
    else {
        src = (z == 4) ? Wq : (z == 5) ? Wk : Wv;
        dst = (z == 4) ? g_wqh : (z == 5) ? g_wkh : g_wvh;
        n4 = HID * HID / 4;
    }
    int i = blockIdx.x * 256 + threadIdx.x;
    int stride = gridDim.x * 256;
    for (; i < n4; i += stride) {
        float4 v = ((const float4*)src)[i];
        ((__half2*)dst)[2*i]   = __floats2half2_rn(v.x, v.y);
        ((__half2*)dst)[2*i+1] = __floats2half2_rn(v.z, v.w);
    }
}

// V transpose (fp16, vectorized 64x64 tiles): g_vt[b][d][s] = g_v[b][s][d]
__global__ void __launch_bounds__(256) vtrans_kernel()
{
    __shared__ __half t[64][66];
    const int z  = blockIdx.z;
    const int s0 = blockIdx.x * 64;
    const int d0 = blockIdx.y * 64;
    const int tid = threadIdx.x;
    const __half* src = g_v  + (size_t)z * SEQ * HID;
    __half*       dst = g_vt + (size_t)z * SEQ * HID;

#pragma unroll
    for (int i = 0; i < 8; i++) {
        int lin = tid + i * 256;
        int s  = lin >> 5;
        int dp = lin & 31;
        __half2 v = *(const __half2*)(src + (size_t)(s0 + s) * HID + d0 + 2 * dp);
        *(__half2*)&t[s][2 * dp] = v;
    }
    __syncthreads();
#pragma unroll
    for (int i = 0; i < 8; i++) {
        int lin = tid + i * 256;
        int d  = lin >> 5;
        int sp = lin & 31;
        __half2 w = __halves2half2(t[2 * sp][d], t[2 * sp + 1][d]);
        *(__half2*)(dst + (size_t)(d0 + d) * SEQ + s0 + 2 * sp) = w;
    }
}

// ---------------- launch ----------------
extern "C" void kernel_launch(void* const* d_in, const int* in_sizes, int n_in,
                              void* d_out, int out_size)
{
    const float* x  = (const float*)d_in[0];
    const float* Wq = (const float*)d_in[1];
    const float* bq = (const float*)d_in[2];
    const float* Wk = (const float*)d_in[3];
    const float* bk = (const float*)d_in[4];
    const float* Wv = (const float*)d_in[5];
    const float* bv = (const float*)d_in[6];
    float* out = (float*)d_out;

    cudaFuncSetAttribute(qkv_kernel,    cudaFuncAttributeMaxDynamicSharedMemorySize, H_SMEM);
    cudaFuncSetAttribute(scores_kernel, cudaFuncAttributeMaxDynamicSharedMemorySize, H_SMEM);
    cudaFuncSetAttribute(av_kernel,     cudaFuncAttributeMaxDynamicSharedMemorySize, H_SMEM);

    dim3 blk(256);
    f2h_all_kernel<<<dim3(512, 1, 7), blk>>>(x, Wq, Wk, Wv);
    qkv_kernel<<<dim3(MTOT / BM, HID / BN, 3), blk, H_SMEM>>>(bq, bk, bv);
    vtrans_kernel<<<dim3(SEQ / 64, HID / 64, BATCH), blk>>>();
    scores_kernel<<<dim3(SEQ / BM, SEQ / BN, BATCH), blk, H_SMEM>>>();
    rowinv_kernel<<<dim3((MTOT * 32 + 255) / 256), blk>>>();
    av_kernel<<<dim3(SEQ / BM, HID / BN, BATCH), blk, H_SMEM>>>(out);
}

// round 16
// speedup vs baseline: 1.5246x; 1.5246x over previous
#include <cuda_runtime.h>
#include <cuda_fp16.h>
#include <math.h>
#include <stdint.h>

#define HID   768
#define SEQ   4096
#define BATCH 4
#define MTOT  (BATCH*SEQ)   // 16384

#define BM 128
#define BN 128
#define BKH 64               // halves per stage (128B rows, XOR swizzle, no pad)
#define NSTG 3

#define H_STAGE 32768        // A 128*128B + B 128*128B
#define H_BOFF  16384
#define H_SMEM  (NSTG*H_STAGE)   // 98304 -> 2 CTAs/SM

// output modes for the GEMM epilogue
#define OM_HALF_BIAS    1    // fp16 store, + bias (qkv)
#define OM_HALF_EXP     2    // fp16 store of exp(acc*alpha) + fused row partial sums (scores)
#define OM_F32_ROWSCALE 3    // fp32 store of acc * rowinv[row] (av)

#define NYT (SEQ / BN)       // 32 column tiles per row (scores)

// ---------------- scratch ----------------
__device__ __half g_xh[(size_t)MTOT * HID];
__device__ __half g_wqh[HID * HID];
__device__ __half g_wkh[HID * HID];
__device__ __half g_wvh[HID * HID];
__device__ __half g_q[(size_t)MTOT * HID];
__device__ __half g_k[(size_t)MTOT * HID];
__device__ __half g_v[(size_t)MTOT * HID];
__device__ __half g_vt[(size_t)MTOT * HID];            // [b][d][s]
__device__ __half g_p[(size_t)BATCH * SEQ * SEQ];      // fp16 unnormalized probs
__device__ float  g_ps[(size_t)MTOT * NYT];            // per-tile row partial sums
__device__ float  g_rs[MTOT];                          // 1 / row sum

// ---------------- helpers ----------------
__device__ __forceinline__ uint32_t smem_u32(const void* p) {
    uint32_t a;
    asm("{ .reg .u64 t; cvta.to.shared.u64 t, %1; cvt.u32.u64 %0, t; }" : "=r"(a) : "l"(p));
    return a;
}
__device__ __forceinline__ void cp16(uint32_t dst, const void* src) {
    asm volatile("cp.async.cg.shared.global [%0], [%1], 16;" :: "r"(dst), "l"(src));
}
__device__ __forceinline__ void cp_commit() {
    asm volatile("cp.async.commit_group;" ::: "memory");
}
template<int N> __device__ __forceinline__ void cp_wait() {
    asm volatile("cp.async.wait_group %0;" :: "n"(N) : "memory");
}
__device__ __forceinline__ void mma16(float* c, const unsigned* a, unsigned b0, unsigned b1) {
    asm volatile(
        "mma.sync.aligned.m16n8k16.row.col.f32.f16.f16.f32 "
        "{%0,%1,%2,%3}, {%4,%5,%6,%7}, {%8,%9}, {%0,%1,%2,%3};"
        : "+f"(c[0]), "+f"(c[1]), "+f"(c[2]), "+f"(c[3])
        : "r"(a[0]), "r"(a[1]), "r"(a[2]), "r"(a[3]), "r"(b0), "r"(b1));
}
__device__ __forceinline__ void ldsm4(unsigned& r0, unsigned& r1, unsigned& r2, unsigned& r3,
                                      uint32_t addr) {
    asm volatile("ldmatrix.sync.aligned.m8n8.x4.shared.b16 {%0,%1,%2,%3}, [%4];"
                 : "=r"(r0), "=r"(r1), "=r"(r2), "=r"(r3) : "r"(addr));
}

// ---------------- fp16 compute core: warp 64x32, k-group range [KG0,KG1) ----------------
// smem tile layout: row r (128B) holds k-chunks ch (16B each) at offset ((ch ^ (r&7))<<4)
template<int KG0, int KG1>
__device__ __forceinline__ void compute_kg(
    uint32_t sA, uint32_t sB, float acc[4][4][4],
    int wm, int wn, int lane)
{
    const int mrow = lane & 7;
    const int mid  = lane >> 3;

    const int aRow = wm + ((mid & 1) << 3) + mrow;
    const int aSw  = aRow & 7;
    const uint32_t aBase = sA + aRow * 128;
    const int aCh = mid >> 1;

    const int bRow = wn + ((mid >> 1) << 3) + mrow;
    const int bSw  = bRow & 7;
    const uint32_t bBase = sB + bRow * 128;
    const int bCh = mid & 1;

#pragma unroll
    for (int kgi = KG0; kgi < KG1; kgi++) {
        const int c0 = kgi * 2;
        unsigned a[4][4], b[4][2];
#pragma unroll
        for (int mi = 0; mi < 4; mi++)
            ldsm4(a[mi][0], a[mi][1], a[mi][2], a[mi][3],
                  aBase + mi * (16 * 128) + (((c0 + aCh) ^ aSw) << 4));
#pragma unroll
        for (int p = 0; p < 2; p++)
            ldsm4(b[2*p][0], b[2*p][1], b[2*p+1][0], b[2*p+1][1],
                  bBase + p * (16 * 128) + (((c0 + bCh) ^ bSw) << 4));
#pragma unroll
        for (int mi = 0; mi < 4; mi++)
#pragma unroll
            for (int ni = 0; ni < 4; ni++)
                mma16(acc[mi][ni], a[mi], b[ni][0], b[ni][1]);
    }
}

// stage loader: 256 threads fill A(128x128B) + B(128x128B) with swizzle
__device__ __forceinline__ void load_stage(
    const __half* __restrict__ A, const __half* __restrict__ Bt,
    int m0, int n0, int lda, int ldb, int k0, uint32_t st, int tid)
{
    const int r  = tid >> 1;
    const int cb = (tid & 1) * 4;
    const int sw = r & 7;
#pragma unroll
    for (int c = 0; c < 4; c++) {
        const int ch = cb + c;
        cp16(st + r * 128 + ((ch ^ sw) << 4),
             A + (size_t)(m0 + r) * lda + k0 + ch * 8);
        cp16(st + H_BOFF + r * 128 + ((ch ^ sw) << 4),
             Bt + (size_t)(n0 + r) * ldb + k0 + ch * 8);
    }
}

// ---------------- fp16 ABT GEMM: D = f(alpha * A * Bt^T) ----------------
template<int OutMode>
__device__ __forceinline__ void gemm_h_body(
    const __half* __restrict__ A, const __half* __restrict__ Bt,
    void* __restrict__ Cv, const float* __restrict__ bias,
    const float* __restrict__ rowinv,
    int K, int lda, int ldb, int ldc, float alpha)
{
    extern __shared__ char smem[];
    const uint32_t sb = smem_u32(smem);

    const int tid  = threadIdx.x;
    const int lane = tid & 31;
    const int warp = tid >> 5;
    const int gid  = lane >> 2;
    const int tig  = lane & 3;
    const int wm   = (warp & 1) * 64;
    const int wn   = (warp >> 1) * 32;
    const int m0 = blockIdx.x * BM, n0 = blockIdx.y * BN;

    float acc[4][4][4];
#pragma unroll
    for (int i = 0; i < 4; i++)
#pragma unroll
        for (int j = 0; j < 4; j++)
#pragma unroll
            for (int l = 0; l < 4; l++) acc[i][j][l] = 0.f;

    const int KT = K / BKH;

#pragma unroll
    for (int s = 0; s < NSTG - 1; s++) {
        load_stage(A, Bt, m0, n0, lda, ldb, s * BKH, sb + s * H_STAGE, tid);
        cp_commit();
    }

    for (int kt = 0; kt < KT; kt++) {
        cp_wait<NSTG - 2>();
        __syncthreads();
        const uint32_t sA = sb + (kt % NSTG) * H_STAGE;
        // k-group 0 first: tensor pipe starts before the load burst
        compute_kg<0, 1>(sA, sA + H_BOFF, acc, wm, wn, lane);
        if (kt + NSTG - 1 < KT)
            load_stage(A, Bt, m0, n0, lda, ldb, (kt + NSTG - 1) * BKH,
                       sb + ((kt + NSTG - 1) % NSTG) * H_STAGE, tid);
        cp_commit();
        compute_kg<1, 4>(sA, sA + H_BOFF, acc, wm, wn, lane);
    }

    // epilogue
    float srow[4][2];   // per-mi row partial sums (OM_HALF_EXP only)
#pragma unroll
    for (int mi = 0; mi < 4; mi++) {
        int r0 = m0 + wm + mi * 16 + gid;
        float i0 = 0.f, i1 = 0.f;
        if (OutMode == OM_F32_ROWSCALE) { i0 = rowinv[r0]; i1 = rowinv[r0 + 8]; }
        if (OutMode == OM_HALF_EXP) { srow[mi][0] = 0.f; srow[mi][1] = 0.f; }
#pragma unroll
        for (int ni = 0; ni < 4; ni++) {
            int c0 = n0 + wn + ni * 8 + 2 * tig;
            if (OutMode == OM_HALF_BIAS) {
                float bb0 = bias[c0], bb1 = bias[c0 + 1];
                __half* C = (__half*)Cv;
                *(__half2*)(C + (size_t)r0 * ldc + c0) =
                    __floats2half2_rn(acc[mi][ni][0] + bb0, acc[mi][ni][1] + bb1);
                *(__half2*)(C + (size_t)(r0 + 8) * ldc + c0) =
                    __floats2half2_rn(acc[mi][ni][2] + bb0, acc[mi][ni][3] + bb1);
            } else if (OutMode == OM_HALF_EXP) {
                float e0 = __expf(acc[mi][ni][0] * alpha);
                float e1 = __expf(acc[mi][ni][1] * alpha);
                float e2 = __expf(acc[mi][ni][2] * alpha);
                float e3 = __expf(acc[mi][ni][3] * alpha);
                srow[mi][0] += e0 + e1;
                srow[mi][1] += e2 + e3;
                __half* C = (__half*)Cv;
                *(__half2*)(C + (size_t)r0 * ldc + c0)       = __floats2half2_rn(e0, e1);
                *(__half2*)(C + (size_t)(r0 + 8) * ldc + c0) = __floats2half2_rn(e2, e3);
            } else { // OM_F32_ROWSCALE
                float* C = (float*)Cv;
                *(float2*)(C + (size_t)r0 * ldc + c0) =
                    make_float2(acc[mi][ni][0] * i0, acc[mi][ni][1] * i0);
                *(float2*)(C + (size_t)(r0 + 8) * ldc + c0) =
                    make_float2(acc[mi][ni][2] * i1, acc[mi][ni][3] * i1);
            }
        }
    }

    // fused row-partial reduction (scores only): deterministic fixed-order
    if (OutMode == OM_HALF_EXP) {
        float* ps = (float*)smem;                   // 128 rows x 4 n-warps
        const int wnid = warp >> 1;                 // n-warp index 0..3
        __syncthreads();                            // mainloop smem reuse
#pragma unroll
        for (int mi = 0; mi < 4; mi++) {
#pragma unroll
            for (int h = 0; h < 2; h++) {
                float s = srow[mi][h];
                s += __shfl_xor_sync(0xffffffffu, s, 1);
                s += __shfl_xor_sync(0xffffffffu, s, 2);
                if (tig == 0) {
                    int rl = wm + mi * 16 + gid + h * 8;   // 0..127
                    ps[rl * 4 + wnid] = s;
                }
            }
        }
        __syncthreads();
        if (tid < 128) {
            float s = ps[tid * 4] + ps[tid * 4 + 1] + ps[tid * 4 + 2] + ps[tid * 4 + 3];
            g_ps[(size_t)(blockIdx.z * SEQ + m0 + tid) * NYT + blockIdx.y] = s;
        }
    }
}

// ---------------- kernels ----------------
__global__ void __launch_bounds__(256, 2) qkv_kernel(
    const float* __restrict__ bq, const float* __restrict__ bk,
    const float* __restrict__ bv)
{
    int z = blockIdx.z;
    const __half* W = (z == 0) ? g_wqh : (z == 1) ? g_wkh : g_wvh;
    const float*  b = (z == 0) ? bq : (z == 1) ? bk : bv;
    __half* out     = (z == 0) ? g_q : (z == 1) ? g_k : g_v;
    gemm_h_body<OM_HALF_BIAS>(g_xh, W, out, b, nullptr, HID, HID, HID, HID, 1.0f);
}

__global__ void __launch_bounds__(256, 2) scores_kernel()
{
    int z = blockIdx.z;
    gemm_h_body<OM_HALF_EXP>(g_q + (size_t)z * SEQ * HID,
                             g_k + (size_t)z * SEQ * HID,
                             g_p + (size_t)z * SEQ * SEQ,
                             nullptr, nullptr, HID, HID, HID, SEQ,
                             0.036084391824351615f);
}

__global__ void __launch_bounds__(256, 2) av_kernel(float* __restrict__ out)
{
    int z = blockIdx.z;
    gemm_h_body<OM_F32_ROWSCALE>(g_p  + (size_t)z * SEQ * SEQ,
                                 g_vt + (size_t)z * SEQ * HID,
                                 out  + (size_t)z * SEQ * HID,
                                 nullptr, g_rs + z * SEQ,
                                 SEQ, SEQ, SEQ, HID, 1.0f);
}

// reduce 32 partials per row -> reciprocal (one warp per row, deterministic)
__global__ void __launch_bounds__(256) rowinv_kernel()
{
    const int wid_g = (blockIdx.x * 256 + threadIdx.x) >> 5;   // global warp = row
    const int lane  = threadIdx.x & 31;
    if (wid_g >= MTOT) return;
    float s = g_ps[(size_t)wid_g * NYT + lane];
#pragma unroll
    for (int o = 16; o; o >>= 1) s += __shfl_xor_sync(0xffffffffu, s, o);
    if (lane == 0) g_rs[wid_g] = 1.0f / s;
}

// fp32 -> fp16 conversion: x (z=0..3 slices) + Wq/Wk/Wv (z=4,5,6)
__global__ void __launch_bounds__(256) f2h_all_kernel(
    const float* __restrict__ x,
    const float* __restrict__ Wq, const float* __restrict__ Wk,
    const float* __restrict__ Wv)
{
    const int z = blockIdx.z;
    const float* src;
    __half* dst;
    int n4;
    const int xq = MTOT * HID / 4 / 4;   // quarter of x in float4s
    if (z < 4) { src = x + (size_t)z * xq * 4; dst = g_xh + (size_t)z * xq * 4; n4 = xq; }
    else {
        src = (z == 4) ? Wq : (z == 5) ? Wk : Wv;
        dst = (z == 4) ? g_wqh : (z == 5) ? g_wkh : g_wvh;
        n4 = HID * HID / 4;
    }
    int i = blockIdx.x * 256 + threadIdx.x;
    int stride = gridDim.x * 256;
    for (; i < n4; i += stride) {
        float4 v = ((const float4*)src)[i];
        ((__half2*)dst)[2*i]   = __floats2half2_rn(v.x, v.y);
        ((__half2*)dst)[2*i+1] = __floats2half2_rn(v.z, v.w);
    }
}

// V transpose (fp16, vectorized 64x64 tiles): g_vt[b][d][s] = g_v[b][s][d]
__global__ void __launch_bounds__(256) vtrans_kernel()
{
    __shared__ __half t[64][66];
    const int z  = blockIdx.z;
    const int s0 = blockIdx.x * 64;
    const int d0 = blockIdx.y * 64;
    const int tid = threadIdx.x;
    const __half* src = g_v  + (size_t)z * SEQ * HID;
    __half*       dst = g_vt + (size_t)z * SEQ * HID;

#pragma unroll
    for (int i = 0; i < 8; i++) {
        int lin = tid + i * 256;
        int s  = lin >> 5;
        int dp = lin & 31;
        __half2 v = *(const __half2*)(src + (size_t)(s0 + s) * HID + d0 + 2 * dp);
        *(__half2*)&t[s][2 * dp] = v;
    }
    __syncthreads();
#pragma unroll
    for (int i = 0; i < 8; i++) {
        int lin = tid + i * 256;
        int d  = lin >> 5;
        int sp = lin & 31;
        __half2 w = __halves2half2(t[2 * sp][d], t[2 * sp + 1][d]);
        *(__half2*)(dst + (size_t)(d0 + d) * SEQ + s0 + 2 * sp) = w;
    }
}

// ---------------- launch ----------------
extern "C" void kernel_launch(void* const* d_in, const int* in_sizes, int n_in,
                              void* d_out, int out_size)
{
    const float* x  = (const float*)d_in[0];
    const float* Wq = (const float*)d_in[1];
    const float* bq = (const float*)d_in[2];
    const float* Wk = (const float*)d_in[3];
    const float* bk = (const float*)d_in[4];
    const float* Wv = (const float*)d_in[5];
    const float* bv = (const float*)d_in[6];
    float* out = (float*)d_out;

    cudaFuncSetAttribute(qkv_kernel,    cudaFuncAttributeMaxDynamicSharedMemorySize, H_SMEM);
    cudaFuncSetAttribute(scores_kernel, cudaFuncAttributeMaxDynamicSharedMemorySize, H_SMEM);
    cudaFuncSetAttribute(av_kernel,     cudaFuncAttributeMaxDynamicSharedMemorySize, H_SMEM);

    dim3 blk(256);
    f2h_all_kernel<<<dim3(512, 1, 7), blk>>>(x, Wq, Wk, Wv);
    qkv_kernel<<<dim3(MTOT / BM, HID / BN, 3), blk, H_SMEM>>>(bq, bk, bv);
    vtrans_kernel<<<dim3(SEQ / 64, HID / 64, BATCH), blk>>>();
    scores_kernel<<<dim3(SEQ / BM, SEQ / BN, BATCH), blk, H_SMEM>>>();
    rowinv_kernel<<<dim3((MTOT * 32 + 255) / 256), blk>>>();
    av_kernel<<<dim3(SEQ / BM, HID / BN, BATCH), blk, H_SMEM>>>(out);
}

// round 17
// speedup vs baseline: 1.5406x; 1.0105x over previous
#include <cuda_runtime.h>
#include <cuda_fp16.h>
#include <math.h>
#include <stdint.h>

#define HID   768
#define SEQ   4096
#define BATCH 4
#define MTOT  (BATCH*SEQ)   // 16384

#define BM 128
#define BN 128
#define BKH 64               // halves per stage (128B rows, XOR swizzle, no pad)
#define NSTG 3

#define H_STAGE 32768        // A 128*128B + B 128*128B
#define H_BOFF  16384
#define H_SMEM  (NSTG*H_STAGE)   // 98304 -> 2 CTAs/SM

// output modes for the GEMM epilogue
#define OM_HALF_BIAS    1    // fp16 store, + bias (qkv q/k)
#define OM_HALF_EXP     2    // fp16 store of exp(acc*alpha) + fused row partial sums (scores)
#define OM_F32_ROWSCALE 3    // fp32 store of acc * rowinv[row] (av)
#define OM_HALF_BIAS_T  4    // fp16 store transposed into g_vt (qkv v)

#define NYT (SEQ / BN)       // 32 column tiles per row (scores)

// ---------------- scratch ----------------
__device__ __half g_xh[(size_t)MTOT * HID];
__device__ __half g_wqh[HID * HID];
__device__ __half g_wkh[HID * HID];
__device__ __half g_wvh[HID * HID];
__device__ __half g_q[(size_t)MTOT * HID];
__device__ __half g_k[(size_t)MTOT * HID];
__device__ __half g_vt[(size_t)MTOT * HID];            // [b][d][s]
__device__ __half g_p[(size_t)BATCH * SEQ * SEQ];      // fp16 unnormalized probs
__device__ float  g_ps[(size_t)MTOT * NYT];            // per-tile row partial sums
__device__ float  g_rs[MTOT];                          // 1 / row sum

// ---------------- helpers ----------------
__device__ __forceinline__ uint32_t smem_u32(const void* p) {
    uint32_t a;
    asm("{ .reg .u64 t; cvta.to.shared.u64 t, %1; cvt.u32.u64 %0, t; }" : "=r"(a) : "l"(p));
    return a;
}
__device__ __forceinline__ void cp16(uint32_t dst, const void* src) {
    asm volatile("cp.async.cg.shared.global [%0], [%1], 16;" :: "r"(dst), "l"(src));
}
__device__ __forceinline__ void cp_commit() {
    asm volatile("cp.async.commit_group;" ::: "memory");
}
template<int N> __device__ __forceinline__ void cp_wait() {
    asm volatile("cp.async.wait_group %0;" :: "n"(N) : "memory");
}
__device__ __forceinline__ void mma16(float* c, const unsigned* a, unsigned b0, unsigned b1) {
    asm volatile(
        "mma.sync.aligned.m16n8k16.row.col.f32.f16.f16.f32 "
        "{%0,%1,%2,%3}, {%4,%5,%6,%7}, {%8,%9}, {%0,%1,%2,%3};"
        : "+f"(c[0]), "+f"(c[1]), "+f"(c[2]), "+f"(c[3])
        : "r"(a[0]), "r"(a[1]), "r"(a[2]), "r"(a[3]), "r"(b0), "r"(b1));
}
__device__ __forceinline__ void ldsm4(unsigned& r0, unsigned& r1, unsigned& r2, unsigned& r3,
                                      uint32_t addr) {
    asm volatile("ldmatrix.sync.aligned.m8n8.x4.shared.b16 {%0,%1,%2,%3}, [%4];"
                 : "=r"(r0), "=r"(r1), "=r"(r2), "=r"(r3) : "r"(addr));
}

// ---------------- fp16 compute core: warp 64x32, k-group range [KG0,KG1) ----------------
// smem tile layout: row r (128B) holds k-chunks ch (16B each) at offset ((ch ^ (r&7))<<4)
// ROT (compile-time) rotates the k-group order by 2 for half the warps: addresses stay
// compile-time constants (the R15 failure was runtime-rotated addressing).
template<int KG0, int KG1, int ROT>
__device__ __forceinline__ void compute_kg(
    uint32_t sA, uint32_t sB, float acc[4][4][4],
    int wm, int wn, int lane)
{
    const int mrow = lane & 7;
    const int mid  = lane >> 3;

    const int aRow = wm + ((mid & 1) << 3) + mrow;
    const int aSw  = aRow & 7;
    const uint32_t aBase = sA + aRow * 128;
    const int aCh = mid >> 1;

    const int bRow = wn + ((mid >> 1) << 3) + mrow;
    const int bSw  = bRow & 7;
    const uint32_t bBase = sB + bRow * 128;
    const int bCh = mid & 1;

#pragma unroll
    for (int kgi = KG0; kgi < KG1; kgi++) {
        const int c0 = (((kgi + 2 * ROT) & 3)) * 2;
        unsigned a[4][4], b[4][2];
#pragma unroll
        for (int mi = 0; mi < 4; mi++)
            ldsm4(a[mi][0], a[mi][1], a[mi][2], a[mi][3],
                  aBase + mi * (16 * 128) + (((c0 + aCh) ^ aSw) << 4));
#pragma unroll
        for (int p = 0; p < 2; p++)
            ldsm4(b[2*p][0], b[2*p][1], b[2*p+1][0], b[2*p+1][1],
                  bBase + p * (16 * 128) + (((c0 + bCh) ^ bSw) << 4));
#pragma unroll
        for (int mi = 0; mi < 4; mi++)
#pragma unroll
            for (int ni = 0; ni < 4; ni++)
                mma16(acc[mi][ni], a[mi], b[ni][0], b[ni][1]);
    }
}

// stage loader: 256 threads fill A(128x128B) + B(128x128B) with swizzle
__device__ __forceinline__ void load_stage(
    const __half* __restrict__ A, const __half* __restrict__ Bt,
    int m0, int n0, int lda, int ldb, int k0, uint32_t st, int tid)
{
    const int r  = tid >> 1;
    const int cb = (tid & 1) * 4;
    const int sw = r & 7;
#pragma unroll
    for (int c = 0; c < 4; c++) {
        const int ch = cb + c;
        cp16(st + r * 128 + ((ch ^ sw) << 4),
             A + (size_t)(m0 + r) * lda + k0 + ch * 8);
        cp16(st + H_BOFF + r * 128 + ((ch ^ sw) << 4),
             Bt + (size_t)(n0 + r) * ldb + k0 + ch * 8);
    }
}

// ---------------- fp16 ABT GEMM: D = f(alpha * A * Bt^T) ----------------
template<int OutMode>
__device__ __forceinline__ void gemm_h_body(
    const __half* __restrict__ A, const __half* __restrict__ Bt,
    void* __restrict__ Cv, const float* __restrict__ bias,
    const float* __restrict__ rowinv,
    int K, int lda, int ldb, int ldc, float alpha)
{
    extern __shared__ char smem[];
    const uint32_t sb = smem_u32(smem);

    const int tid  = threadIdx.x;
    const int lane = tid & 31;
    const int warp = tid >> 5;
    const int gid  = lane >> 2;
    const int tig  = lane & 3;
    const int wm   = (warp & 1) * 64;
    const int wn   = (warp >> 1) * 32;
    const int rph  = (warp >> 2) & 1;   // rotation phase
    const int m0 = blockIdx.x * BM, n0 = blockIdx.y * BN;

    float acc[4][4][4];
#pragma unroll
    for (int i = 0; i < 4; i++)
#pragma unroll
        for (int j = 0; j < 4; j++)
#pragma unroll
            for (int l = 0; l < 4; l++) acc[i][j][l] = 0.f;

    const int KT = K / BKH;

#pragma unroll
    for (int s = 0; s < NSTG - 1; s++) {
        load_stage(A, Bt, m0, n0, lda, ldb, s * BKH, sb + s * H_STAGE, tid);
        cp_commit();
    }

    for (int kt = 0; kt < KT; kt++) {
        cp_wait<NSTG - 2>();
        __syncthreads();
        const uint32_t sA = sb + (kt % NSTG) * H_STAGE;
        // first k-group (per-half rotated): tensor pipe starts before the load burst
        if (rph == 0) compute_kg<0, 1, 0>(sA, sA + H_BOFF, acc, wm, wn, lane);
        else          compute_kg<0, 1, 1>(sA, sA + H_BOFF, acc, wm, wn, lane);
        if (kt + NSTG - 1 < KT)
            load_stage(A, Bt, m0, n0, lda, ldb, (kt + NSTG - 1) * BKH,
                       sb + ((kt + NSTG - 1) % NSTG) * H_STAGE, tid);
        cp_commit();
        if (rph == 0) compute_kg<1, 4, 0>(sA, sA + H_BOFF, acc, wm, wn, lane);
        else          compute_kg<1, 4, 1>(sA, sA + H_BOFF, acc, wm, wn, lane);
    }

    // epilogue
    float srow[4][2];   // per-mi row partial sums (OM_HALF_EXP only)
#pragma unroll
    for (int mi = 0; mi < 4; mi++) {
        int r0 = m0 + wm + mi * 16 + gid;
        float i0 = 0.f, i1 = 0.f;
        if (OutMode == OM_F32_ROWSCALE) { i0 = rowinv[r0]; i1 = rowinv[r0 + 8]; }
        if (OutMode == OM_HALF_EXP) { srow[mi][0] = 0.f; srow[mi][1] = 0.f; }
#pragma unroll
        for (int ni = 0; ni < 4; ni++) {
            int c0 = n0 + wn + ni * 8 + 2 * tig;
            if (OutMode == OM_HALF_BIAS) {
                float bb0 = bias[c0], bb1 = bias[c0 + 1];
                __half* C = (__half*)Cv;
                *(__half2*)(C + (size_t)r0 * ldc + c0) =
                    __floats2half2_rn(acc[mi][ni][0] + bb0, acc[mi][ni][1] + bb1);
                *(__half2*)(C + (size_t)(r0 + 8) * ldc + c0) =
                    __floats2half2_rn(acc[mi][ni][2] + bb0, acc[mi][ni][3] + bb1);
            } else if (OutMode == OM_HALF_BIAS_T) {
                // stage into smem tile [128][130] (local coords), transpose after
                float bb0 = bias[c0], bb1 = bias[c0 + 1];
                __half* tile = (__half*)smem;
                int rl = wm + mi * 16 + gid;
                int cl = wn + ni * 8 + 2 * tig;
                *(__half2*)(tile + rl * 130 + cl) =
                    __floats2half2_rn(acc[mi][ni][0] + bb0, acc[mi][ni][1] + bb1);
                *(__half2*)(tile + (rl + 8) * 130 + cl) =
                    __floats2half2_rn(acc[mi][ni][2] + bb0, acc[mi][ni][3] + bb1);
            } else if (OutMode == OM_HALF_EXP) {
                float e0 = __expf(acc[mi][ni][0] * alpha);
                float e1 = __expf(acc[mi][ni][1] * alpha);
                float e2 = __expf(acc[mi][ni][2] * alpha);
                float e3 = __expf(acc[mi][ni][3] * alpha);
                srow[mi][0] += e0 + e1;
                srow[mi][1] += e2 + e3;
                __half* C = (__half*)Cv;
                *(__half2*)(C + (size_t)r0 * ldc + c0)       = __floats2half2_rn(e0, e1);
                *(__half2*)(C + (size_t)(r0 + 8) * ldc + c0) = __floats2half2_rn(e2, e3);
            } else { // OM_F32_ROWSCALE
                float* C = (float*)Cv;
                *(float2*)(C + (size_t)r0 * ldc + c0) =
                    make_float2(acc[mi][ni][0] * i0, acc[mi][ni][1] * i0);
                *(float2*)(C + (size_t)(r0 + 8) * ldc + c0) =
                    make_float2(acc[mi][ni][2] * i1, acc[mi][ni][3] * i1);
            }
        }
    }

    // transposed store for V: g_vt[b][d][s] = tile[s_local][d_local]
    if (OutMode == OM_HALF_BIAS_T) {
        __syncthreads();
        const __half* tile = (const __half*)smem;
        const int b  = m0 >> 12;            // batch (BM divides SEQ)
        const int s0 = m0 & (SEQ - 1);      // seq offset within batch
        __half* dst = g_vt + (size_t)b * SEQ * HID;
#pragma unroll
        for (int i = 0; i < 32; i++) {
            int lin = tid + i * 256;        // 0..8191: 128 d x 64 s-pairs
            int d  = lin >> 6;
            int sp = lin & 63;
            __half2 w = __halves2half2(tile[(2 * sp) * 130 + d],
                                       tile[(2 * sp + 1) * 130 + d]);
            *(__half2*)(dst + (size_t)(n0 + d) * SEQ + s0 + 2 * sp) = w;
        }
    }

    // fused row-partial reduction (scores only): deterministic fixed-order
    if (OutMode == OM_HALF_EXP) {
        float* ps = (float*)smem;                   // 128 rows x 4 n-warps
        const int wnid = warp >> 1;                 // n-warp index 0..3
        __syncthreads();                            // mainloop smem reuse
#pragma unroll
        for (int mi = 0; mi < 4; mi++) {
#pragma unroll
            for (int h = 0; h < 2; h++) {
                float s = srow[mi][h];
                s += __shfl_xor_sync(0xffffffffu, s, 1);
                s += __shfl_xor_sync(0xffffffffu, s, 2);
                if (tig == 0) {
                    int rl = wm + mi * 16 + gid + h * 8;   // 0..127
                    ps[rl * 4 + wnid] = s;
                }
            }
        }
        __syncthreads();
        if (tid < 128) {
            float s = ps[tid * 4] + ps[tid * 4 + 1] + ps[tid * 4 + 2] + ps[tid * 4 + 3];
            g_ps[(size_t)(blockIdx.z * SEQ + m0 + tid) * NYT + blockIdx.y] = s;
        }
    }
}

// ---------------- kernels ----------------
__global__ void __launch_bounds__(256, 2) qkv_kernel(
    const float* __restrict__ bq, const float* __restrict__ bk,
    const float* __restrict__ bv)
{
    int z = blockIdx.z;
    if (z == 2) {
        gemm_h_body<OM_HALF_BIAS_T>(g_xh, g_wvh, nullptr, bv, nullptr,
                                    HID, HID, HID, HID, 1.0f);
    } else {
        const __half* W = (z == 0) ? g_wqh : g_wkh;
        const float*  b = (z == 0) ? bq : bk;
        __half* out     = (z == 0) ? g_q : g_k;
        gemm_h_body<OM_HALF_BIAS>(g_xh, W, out, b, nullptr, HID, HID, HID, HID, 1.0f);
    }
}

__global__ void __launch_bounds__(256, 2) scores_kernel()
{
    int z = blockIdx.z;
    gemm_h_body<OM_HALF_EXP>(g_q + (size_t)z * SEQ * HID,
                             g_k + (size_t)z * SEQ * HID,
                             g_p + (size_t)z * SEQ * SEQ,
                             nullptr, nullptr, HID, HID, HID, SEQ,
                             0.036084391824351615f);
}

__global__ void __launch_bounds__(256, 2) av_kernel(float* __restrict__ out)
{
    int z = blockIdx.z;
    gemm_h_body<OM_F32_ROWSCALE>(g_p  + (size_t)z * SEQ * SEQ,
                                 g_vt + (size_t)z * SEQ * HID,
                                 out  + (size_t)z * SEQ * HID,
                                 nullptr, g_rs + z * SEQ,
                                 SEQ, SEQ, SEQ, HID, 1.0f);
}

// reduce 32 partials per row -> reciprocal (one warp per row, deterministic)
__global__ void __launch_bounds__(256) rowinv_kernel()
{
    const int wid_g = (blockIdx.x * 256 + threadIdx.x) >> 5;   // global warp = row
    const int lane  = threadIdx.x & 31;
    if (wid_g >= MTOT) return;
    float s = g_ps[(size_t)wid_g * NYT + lane];
#pragma unroll
    for (int o = 16; o; o >>= 1) s += __shfl_xor_sync(0xffffffffu, s, o);
    if (lane == 0) g_rs[wid_g] = 1.0f / s;
}

// fp32 -> fp16 conversion: x (z=0..3 slices) + Wq/Wk/Wv (z=4,5,6)
__global__ void __launch_bounds__(256) f2h_all_kernel(
    const float* __restrict__ x,
    const float* __restrict__ Wq, const float* __restrict__ Wk,
    const float* __restrict__ Wv)
{
    const int z = blockIdx.z;
    const float* src;
    __half* dst;
    int n4;
    const int xq = MTOT * HID / 4 / 4;   // quarter of x in float4s
    if (z < 4) { src = x + (size_t)z * xq * 4; dst = g_xh + (size_t)z * xq * 4; n4 = xq; }
    else {
        src = (z == 4) ? Wq : (z == 5) ? Wk : Wv;
        dst = (z == 4) ? g_wqh : (z == 5) ? g_wkh : g_wvh;
        n4 = HID * HID / 4;
    }
    int i = blockIdx.x * 256 + threadIdx.x;
    int stride = gridDim.x * 256;
    for (; i < n4; i += stride) {
        float4 v = ((const float4*)src)[i];
        ((__half2*)dst)[2*i]   = __floats2half2_rn(v.x, v.y);
        ((__half2*)dst)[2*i+1] = __floats2half2_rn(v.z, v.w);
    }
}

// ---------------- launch ----------------
extern "C" void kernel_launch(void* const* d_in, const int* in_sizes, int n_in,
                              void* d_out, int out_size)
{
    const float* x  = (const float*)d_in[0];
    const float* Wq = (const float*)d_in[1];
    const float* bq = (const float*)d_in[2];
    const float* Wk = (const float*)d_in[3];
    const float* bk = (const float*)d_in[4];
    const float* Wv = (const float*)d_in[5];
    const float* bv = (const float*)d_in[6];
    float* out = (float*)d_out;

    cudaFuncSetAttribute(qkv_kernel,    cudaFuncAttributeMaxDynamicSharedMemorySize, H_SMEM);
    cudaFuncSetAttribute(scores_kernel, cudaFuncAttributeMaxDynamicSharedMemorySize, H_SMEM);
    cudaFuncSetAttribute(av_kernel,     cudaFuncAttributeMaxDynamicSharedMemorySize, H_SMEM);

    dim3 blk(256);
    f2h_all_kernel<<<dim3(512, 1, 7), blk>>>(x, Wq, Wk, Wv);
    qkv_kernel<<<dim3(MTOT / BM, HID / BN, 3), blk, H_SMEM>>>(bq, bk, bv);
    scores_kernel<<<dim3(SEQ / BM, SEQ / BN, BATCH), blk, H_SMEM>>>();
    rowinv_kernel<<<dim3((MTOT * 32 + 255) / 256), blk>>>();
    av_kernel<<<dim3(SEQ / BM, HID / BN, BATCH), blk, H_SMEM>>>(out);
}